// round 16
// baseline (speedup 1.0000x reference)
#include <cuda_runtime.h>
#include <cuda_bf16.h>
#include <cuda_fp16.h>
#include <math.h>
#include <stdint.h>

#define B_  8192
#define D_  768
#define GH_ 384
#define E_  8
#define H_  3072

#define OFF_GATE ((size_t)B_ * D_)
#define OFF_EO   (OFF_GATE + (size_t)B_ * E_)

// Scratch
__device__ float g_g[(size_t)B_ * GH_];
__device__ __align__(16) __nv_bfloat16 g_hhi[(size_t)B_ * D_];   // gating path (exact)
__device__ __align__(16) __nv_bfloat16 g_hlo[(size_t)B_ * D_];
__device__ __align__(16) __nv_bfloat16 g_gw1hi[(size_t)GH_ * D_];
__device__ __align__(16) __nv_bfloat16 g_gw1lo[(size_t)GH_ * D_];
__device__ __align__(16) __half g_hf[(size_t)B_ * D_];           // fp16 expert path
__device__ __align__(16) __half g_w1f[(size_t)E_ * H_ * D_];
__device__ __align__(16) __half g_w2f[(size_t)E_ * D_ * H_];
__device__ __align__(16) __half g_hidf[(size_t)E_ * B_ * H_];
__device__ float g_tw[B_ * 2];
__device__ int   g_ti[B_ * 2];

__device__ __forceinline__ uint32_t smem_to_u32(const void* p) {
    uint32_t a;
    asm("{ .reg .u64 t; cvta.to.shared.u64 t, %1; cvt.u32.u64 %0, t; }" : "=r"(a) : "l"(p));
    return a;
}
// Fast exact-form gelu (A&S 7.1.26 erf, abs err 1.5e-7)
__device__ __forceinline__ float gelu_fast(float x) {
    float xs = x * 0.7071067811865476f;
    float ax = fabsf(xs);
    float t  = __fdividef(1.0f, fmaf(0.3275911f, ax, 1.0f));
    float y  = t * fmaf(t, fmaf(t, fmaf(t, fmaf(t, 1.061405429f, -1.453152027f),
                                        1.421413741f), -0.284496736f), 0.254829592f);
    float ev = 1.0f - y * __expf(-ax * ax);
    ev = copysignf(ev, xs);
    return 0.5f * x * (1.0f + ev);
}
__device__ __forceinline__ void splitbf(float v, __nv_bfloat16& h, __nv_bfloat16& l) {
    h = __float2bfloat16(v);
    l = __float2bfloat16(v - __bfloat162float(h));
}
__device__ __forceinline__ uint32_t packh2(float v0, float v1) {
    uint32_t p;
    asm("cvt.rn.f16x2.f32 %0, %1, %2;" : "=r"(p) : "f"(v1), "f"(v0));
    return p;  // lo half = v0
}
__device__ __forceinline__ void cpa16(uint32_t dst, const void* src) {
    asm volatile("cp.async.cg.shared.global [%0], [%1], 16;" :: "r"(dst), "l"(src));
}
// .ca variant: cache in L1 — used for A tiles shared by co-resident CTA pairs
__device__ __forceinline__ void cpa16_ca(uint32_t dst, const void* src) {
    asm volatile("cp.async.ca.shared.global [%0], [%1], 16;" :: "r"(dst), "l"(src));
}
// Streaming (evict-first) stores for write-once data
__device__ __forceinline__ void st_cs_b32(void* p, uint32_t v) {
    asm volatile("st.global.cs.b32 [%0], %1;" :: "l"(p), "r"(v));
}
__device__ __forceinline__ void st_cs_f2(void* p, float a, float b) {
    asm volatile("st.global.cs.v2.f32 [%0], {%1, %2};" :: "l"(p), "f"(a), "f"(b));
}
#define CP_COMMIT() asm volatile("cp.async.commit_group;" ::: "memory")
#define CP_WAIT1()  asm volatile("cp.async.wait_group 1;" ::: "memory")
#define CP_WAIT0()  asm volatile("cp.async.wait_group 0;" ::: "memory")

#define LDSM4(r, addr)                                                          \
    asm volatile("ldmatrix.sync.aligned.m8n8.x4.shared.b16 {%0,%1,%2,%3}, [%4];"\
                 : "=r"((r)[0]), "=r"((r)[1]), "=r"((r)[2]), "=r"((r)[3])       \
                 : "r"(addr))

#define MMA_BF16(d, a, b0, b1)                                                  \
    asm volatile("mma.sync.aligned.m16n8k16.row.col.f32.bf16.bf16.f32 "         \
                 "{%0,%1,%2,%3}, {%4,%5,%6,%7}, {%8,%9}, {%0,%1,%2,%3};"        \
                 : "+f"((d)[0]), "+f"((d)[1]), "+f"((d)[2]), "+f"((d)[3])       \
                 : "r"((a)[0]), "r"((a)[1]), "r"((a)[2]), "r"((a)[3]),          \
                   "r"(b0), "r"(b1))

#define MMA_F16(d, a, b0, b1)                                                   \
    asm volatile("mma.sync.aligned.m16n8k16.row.col.f32.f16.f16.f32 "           \
                 "{%0,%1,%2,%3}, {%4,%5,%6,%7}, {%8,%9}, {%0,%1,%2,%3};"        \
                 : "+f"((d)[0]), "+f"((d)[1]), "+f"((d)[2]), "+f"((d)[3])       \
                 : "r"((a)[0]), "r"((a)[1]), "r"((a)[2]), "r"((a)[3]),          \
                   "r"(b0), "r"(b1))

// ---------------------------------------------------------------------------
// LayerNorm: bf16 hi/lo (gating) + fp16 single plane (experts)
// ---------------------------------------------------------------------------
__global__ void ln_kernel(const float* __restrict__ x,
                          const float* __restrict__ gamma,
                          const float* __restrict__ beta) {
    int b = blockIdx.x;
    const float* row = x + (size_t)b * D_;
    float s = 0.f, s2 = 0.f;
    for (int i = threadIdx.x; i < D_; i += blockDim.x) {
        float v = row[i];
        s += v; s2 += v * v;
    }
    __shared__ float red[64];
    for (int o = 16; o; o >>= 1) {
        s  += __shfl_down_sync(0xffffffffu, s,  o);
        s2 += __shfl_down_sync(0xffffffffu, s2, o);
    }
    int wid = threadIdx.x >> 5, lid = threadIdx.x & 31;
    if (lid == 0) { red[wid] = s; red[wid + 32] = s2; }
    __syncthreads();
    int nw = blockDim.x >> 5;
    if (wid == 0) {
        s  = (lid < nw) ? red[lid]      : 0.f;
        s2 = (lid < nw) ? red[lid + 32] : 0.f;
        for (int o = 16; o; o >>= 1) {
            s  += __shfl_down_sync(0xffffffffu, s,  o);
            s2 += __shfl_down_sync(0xffffffffu, s2, o);
        }
        if (lid == 0) { red[0] = s; red[1] = s2; }
    }
    __syncthreads();
    float mu   = red[0] / D_;
    float var  = red[1] / D_ - mu * mu;
    float rstd = rsqrtf(var + 1e-5f);
    for (int i = threadIdx.x; i < D_; i += blockDim.x) {
        float v = (row[i] - mu) * rstd * gamma[i] + beta[i];
        size_t idx = (size_t)b * D_ + i;
        __nv_bfloat16 hi, lo;
        splitbf(v, hi, lo);
        g_hhi[idx] = hi;
        g_hlo[idx] = lo;
        g_hf[idx]  = __float2half_rn(v);
    }
}

// ---------------------------------------------------------------------------
// Transposes: fp16 single-plane (expert weights) and bf16 split (gating)
// ---------------------------------------------------------------------------
__global__ void transpose_f16_kernel(const float* __restrict__ src,
                                     __half* __restrict__ dst, int R, int C) {
    __shared__ float t[32][33];
    int e = blockIdx.z;
    int c0 = blockIdx.x * 32, r0 = blockIdx.y * 32;
    const float* s = src + (size_t)e * R * C;
    #pragma unroll
    for (int i = 0; i < 32; i += 8)
        t[threadIdx.y + i][threadIdx.x] =
            s[(size_t)(r0 + threadIdx.y + i) * C + c0 + threadIdx.x];
    __syncthreads();
    size_t ob = (size_t)e * C * R;
    #pragma unroll
    for (int i = 0; i < 32; i += 8)
        dst[ob + (size_t)(c0 + threadIdx.y + i) * R + r0 + threadIdx.x] =
            __float2half_rn(t[threadIdx.x][threadIdx.y + i]);
}

__global__ void transpose_split_kernel(const float* __restrict__ src,
                                       __nv_bfloat16* __restrict__ dhi,
                                       __nv_bfloat16* __restrict__ dlo,
                                       int R, int C) {
    __shared__ float t[32][33];
    int c0 = blockIdx.x * 32, r0 = blockIdx.y * 32;
    #pragma unroll
    for (int i = 0; i < 32; i += 8)
        t[threadIdx.y + i][threadIdx.x] =
            src[(size_t)(r0 + threadIdx.y + i) * C + c0 + threadIdx.x];
    __syncthreads();
    #pragma unroll
    for (int i = 0; i < 32; i += 8) {
        float v = t[threadIdx.x][threadIdx.y + i];
        __nv_bfloat16 hi, lo;
        splitbf(v, hi, lo);
        size_t o = (size_t)(c0 + threadIdx.y + i) * R + r0 + threadIdx.x;
        dhi[o] = hi;
        dlo[o] = lo;
    }
}

// ---------------------------------------------------------------------------
// fp16 single-plane GEMM: 128x128x64 CTA chunks, 8 warps 64x32, 256 thr,
// 128B-pitch SW128-swizzled smem (seg ^= row&7), 3-stage pipeline, 2 CTAs/SM.
// A tiles loaded with .ca (shared by co-resident CTA pair), B with .cg.
// hid/EO written with streaming (.cs) stores to preserve L2 for operands.
// OUT_MODE: 2 = gelu + fp16 out (GEMM1), 3 = fp32 +bias + fused combine (GEMM2)
// ---------------------------------------------------------------------------
#define FPLANE 16384                     // 128 rows * 128B
#define FSTAGE (2 * FPLANE)              // A|B = 32768
#define FNSTG 3
#define SMEM_F (FNSTG * FSTAGE)          // 98304

template <int OUT_MODE>
__global__ void __launch_bounds__(256, 2) gemm_f16(
    const __half* __restrict__ Ah, const __half* __restrict__ Bh,
    const float* __restrict__ bias,
    __half* __restrict__ OutH, float* __restrict__ OutF, float* __restrict__ Res,
    int Ktot, size_t aStrideE, size_t bStrideE, size_t biasStrideE,
    size_t cStrideE, int ldc, int cColStride)
{
    extern __shared__ char smem[];
    uint32_t sbase = smem_to_u32(smem);
    int tid  = threadIdx.x;
    int warp = tid >> 5, lane = tid & 31;
    int e  = blockIdx.z;
    int bm = blockIdx.y * 128;
    int bn = blockIdx.x * 128;
    int wm = (warp >> 2) * 64;
    int wn = (warp & 3)  * 32;
    int g  = lane >> 2, tg = lane & 3;
    int mi = lane >> 3, rr = lane & 7;

    const __half* pA = Ah + (size_t)e * aStrideE + (size_t)bm * Ktot;
    const __half* pB = Bh + (size_t)e * bStrideE + (size_t)bn * Ktot;

    // ldmatrix lane addressing (128B pitch, seg ^= row&7 on 16B segments)
    int arow = wm + (mi & 1) * 8 + rr;
    uint32_t aoff = (uint32_t)arow * 128;
    int aswz = arow & 7;
    int akseg = mi >> 1;                 // 16B half within each k16 step
    int brow = wn + (mi >> 1) * 8 + rr;
    uint32_t boff = (uint32_t)brow * 128;
    int bswz = brow & 7;
    int bkseg = mi & 1;

    float acc[4][4][4];
    #pragma unroll
    for (int i = 0; i < 4; i++)
        #pragma unroll
        for (int j = 0; j < 4; j++)
            #pragma unroll
            for (int r = 0; r < 4; r++) acc[i][j][r] = 0.f;

    const int NC = Ktot / 64;

    auto load_chunk = [&](int c, int st) {
        int k0 = c * 64;
        uint32_t sb = sbase + (uint32_t)st * FSTAGE;
        #pragma unroll
        for (int i = 0; i < 4; i++) {            // 1024 16B units per plane
            int p = tid + i * 256;
            int row = p >> 3, seg = p & 7;
            uint32_t d = sb + (uint32_t)row * 128
                       + (uint32_t)((seg ^ (row & 7)) << 4);
            size_t go = (size_t)row * Ktot + k0 + seg * 8;
            cpa16_ca(d,       pA + go);          // A: L1-cached (pair reuse)
            cpa16(d + FPLANE, pB + go);          // B: L2 only
        }
        CP_COMMIT();
    };

    load_chunk(0, 0);
    if (NC > 1) load_chunk(1, 1);

    for (int c = 0; c < NC; c++) {
        if (c + 1 < NC) { CP_WAIT1(); } else { CP_WAIT0(); }
        __syncthreads();
        // Stage (c+2)%3 consumed in iter c-1 (ordered by sync above): refill now.
        if (c + 2 < NC) load_chunk(c + 2, (c + 2) % FNSTG);

        uint32_t sb = sbase + (uint32_t)((c % FNSTG) * FSTAGE);
        #pragma unroll
        for (int ks = 0; ks < 4; ks++) {         // 4 k16 steps per chunk
            uint32_t af[4][4], bf[2][4];
            #pragma unroll
            for (int i = 0; i < 4; i++) {
                uint32_t ad = sb + aoff + (uint32_t)i * 2048
                            + (uint32_t)(((ks * 2 + akseg) ^ aswz) << 4);
                LDSM4(af[i], ad);
            }
            #pragma unroll
            for (int jp = 0; jp < 2; jp++) {
                uint32_t bd = sb + FPLANE + boff + (uint32_t)jp * 2048
                            + (uint32_t)(((ks * 2 + bkseg) ^ bswz) << 4);
                LDSM4(bf[jp], bd);
            }
            #pragma unroll
            for (int i = 0; i < 4; i++)
                #pragma unroll
                for (int j = 0; j < 4; j++) {
                    int jp = j >> 1, hf = (j & 1) * 2;
                    MMA_F16(acc[i][j], af[i], bf[jp][hf], bf[jp][hf + 1]);
                }
        }
    }

    const float* bp = bias + (size_t)e * biasStrideE;
    #pragma unroll
    for (int i = 0; i < 4; i++) {
        int r0 = bm + wm + i * 16 + g;
        float cw0 = 0.f, cw1 = 0.f;
        if (OUT_MODE == 3) {
            int i00 = g_ti[r0 * 2], i01 = g_ti[r0 * 2 + 1];
            cw0 = (i00 == e) ? g_tw[r0 * 2] : ((i01 == e) ? g_tw[r0 * 2 + 1] : 0.f);
            int r1 = r0 + 8;
            int i10 = g_ti[r1 * 2], i11 = g_ti[r1 * 2 + 1];
            cw1 = (i10 == e) ? g_tw[r1 * 2] : ((i11 == e) ? g_tw[r1 * 2 + 1] : 0.f);
        }
        #pragma unroll
        for (int j = 0; j < 4; j++) {
            int c0 = bn + wn + j * 8 + tg * 2;
            float bi0 = bp[c0], bi1 = bp[c0 + 1];
            float v0 = acc[i][j][0] + bi0, v1 = acc[i][j][1] + bi1;
            float v2 = acc[i][j][2] + bi0, v3 = acc[i][j][3] + bi1;
            size_t rbA = (size_t)e * cStrideE + (size_t)r0 * ldc
                       + (size_t)e * cColStride + c0;
            size_t rbB = rbA + (size_t)8 * ldc;
            if (OUT_MODE == 3) {
                st_cs_f2(OutF + rbA, v0, v1);
                st_cs_f2(OutF + rbB, v2, v3);
                if (cw0 != 0.f) {
                    atomicAdd(&Res[(size_t)r0 * D_ + c0],     cw0 * v0);
                    atomicAdd(&Res[(size_t)r0 * D_ + c0 + 1], cw0 * v1);
                }
                if (cw1 != 0.f) {
                    atomicAdd(&Res[(size_t)(r0 + 8) * D_ + c0],     cw1 * v2);
                    atomicAdd(&Res[(size_t)(r0 + 8) * D_ + c0 + 1], cw1 * v3);
                }
            } else {  // OUT_MODE 2: gelu + fp16, streaming store
                v0 = gelu_fast(v0); v1 = gelu_fast(v1);
                v2 = gelu_fast(v2); v3 = gelu_fast(v3);
                st_cs_b32(OutH + rbA, packh2(v0, v1));
                st_cs_b32(OutH + rbB, packh2(v2, v3));
            }
        }
    }
}

// ---------------------------------------------------------------------------
// Exact bf16x3 gating GEMM (unchanged math, gelu fp32 out)
// ---------------------------------------------------------------------------
#define PLANE_B 8192
#define STAGE_B (4 * PLANE_B)
#define NSTG 3
#define SMEM_TC (NSTG * STAGE_B)

__global__ void __launch_bounds__(256, 2) gemm_gate(
    const __nv_bfloat16* __restrict__ Ahi, const __nv_bfloat16* __restrict__ Alo,
    const __nv_bfloat16* __restrict__ Bhi, const __nv_bfloat16* __restrict__ Blo,
    const float* __restrict__ bias, float* __restrict__ OutF,
    int Ktot, int ldc)
{
    extern __shared__ char smem[];
    uint32_t sbase = smem_to_u32(smem);
    int tid  = threadIdx.x;
    int warp = tid >> 5, lane = tid & 31;
    int bm = blockIdx.y * 128;
    int bn = blockIdx.x * 128;
    int wm = (warp >> 2) * 64;
    int wn = (warp & 3)  * 32;
    int g  = lane >> 2, tg = lane & 3;
    int mi = lane >> 3, rr = lane & 7;

    const __nv_bfloat16* pAhi = Ahi + (size_t)bm * Ktot;
    const __nv_bfloat16* pAlo = Alo + (size_t)bm * Ktot;
    const __nv_bfloat16* pBhi = Bhi + (size_t)bn * Ktot;
    const __nv_bfloat16* pBlo = Blo + (size_t)bn * Ktot;

    int arow = wm + (mi & 1) * 8 + rr;
    uint32_t aoff = (uint32_t)arow * 64;
    uint32_t aswz = (uint32_t)(((arow >> 1) & 3) << 4);
    int akseg = mi >> 1;
    int brow = wn + (mi >> 1) * 8 + rr;
    uint32_t boff = (uint32_t)brow * 64;
    uint32_t bswz = (uint32_t)(((brow >> 1) & 3) << 4);
    int bkseg = mi & 1;

    float acc[4][4][4];
    #pragma unroll
    for (int i = 0; i < 4; i++)
        #pragma unroll
        for (int j = 0; j < 4; j++)
            #pragma unroll
            for (int r = 0; r < 4; r++) acc[i][j][r] = 0.f;

    const int NC = Ktot / 32;

    auto load_chunk = [&](int c, int st) {
        int k0 = c * 32;
        uint32_t sb = sbase + (uint32_t)st * STAGE_B;
        #pragma unroll
        for (int i = 0; i < 2; i++) {
            int p = tid + i * 256;
            int row = p >> 2, col = p & 3;
            uint32_t d = sb + (uint32_t)row * 64
                       + (uint32_t)((col ^ ((row >> 1) & 3)) << 4);
            size_t go = (size_t)row * Ktot + k0 + col * 8;
            cpa16_ca(d,              pAhi + go);
            cpa16_ca(d + PLANE_B,    pAlo + go);
            cpa16(d + 2u * PLANE_B,  pBhi + go);
            cpa16(d + 3u * PLANE_B,  pBlo + go);
        }
        CP_COMMIT();
    };

    load_chunk(0, 0);
    if (NC > 1) load_chunk(1, 1);

    for (int c = 0; c < NC; c++) {
        if (c + 1 < NC) { CP_WAIT1(); } else { CP_WAIT0(); }
        __syncthreads();
        if (c + 2 < NC) load_chunk(c + 2, (c + 2) % NSTG);

        uint32_t sb = sbase + (uint32_t)((c % NSTG) * STAGE_B);
        #pragma unroll
        for (int ks = 0; ks < 2; ks++) {
            uint32_t ah[4][4], al[4][4], bh[2][4], bl[2][4];
            #pragma unroll
            for (int i = 0; i < 4; i++) {
                uint32_t ad = sb + aoff + (uint32_t)i * 1024
                            + (((uint32_t)(ks * 2 + akseg) << 4) ^ aswz);
                LDSM4(ah[i], ad);
                LDSM4(al[i], ad + PLANE_B);
            }
            #pragma unroll
            for (int jp = 0; jp < 2; jp++) {
                uint32_t bd = sb + 2u * PLANE_B + boff + (uint32_t)jp * 1024
                            + (((uint32_t)(ks * 2 + bkseg) << 4) ^ bswz);
                LDSM4(bh[jp], bd);
                LDSM4(bl[jp], bd + PLANE_B);
            }
            #pragma unroll
            for (int i = 0; i < 4; i++)
                #pragma unroll
                for (int j = 0; j < 4; j++) {
                    int jp = j >> 1, hf = (j & 1) * 2;
                    MMA_BF16(acc[i][j], ah[i], bh[jp][hf], bh[jp][hf + 1]);
                }
            #pragma unroll
            for (int i = 0; i < 4; i++)
                #pragma unroll
                for (int j = 0; j < 4; j++) {
                    int jp = j >> 1, hf = (j & 1) * 2;
                    MMA_BF16(acc[i][j], ah[i], bl[jp][hf], bl[jp][hf + 1]);
                }
            #pragma unroll
            for (int i = 0; i < 4; i++)
                #pragma unroll
                for (int j = 0; j < 4; j++) {
                    int jp = j >> 1, hf = (j & 1) * 2;
                    MMA_BF16(acc[i][j], al[i], bh[jp][hf], bh[jp][hf + 1]);
                }
        }
    }

    #pragma unroll
    for (int i = 0; i < 4; i++) {
        int r0 = bm + wm + i * 16 + g;
        #pragma unroll
        for (int j = 0; j < 4; j++) {
            int c0 = bn + wn + j * 8 + tg * 2;
            float bi0 = bias[c0], bi1 = bias[c0 + 1];
            size_t rbA = (size_t)r0 * ldc + c0;
            size_t rbB = rbA + (size_t)8 * ldc;
            OutF[rbA]     = gelu_fast(acc[i][j][0] + bi0);
            OutF[rbA + 1] = gelu_fast(acc[i][j][1] + bi1);
            OutF[rbB]     = gelu_fast(acc[i][j][2] + bi0);
            OutF[rbB + 1] = gelu_fast(acc[i][j][3] + bi1);
        }
    }
}

// ---------------------------------------------------------------------------
__global__ void gate_kernel(const float* __restrict__ gw2,
                            const float* __restrict__ gb2,
                            float* __restrict__ dout) {
    int b = blockIdx.x * (blockDim.x >> 5) + (threadIdx.x >> 5);
    if (b >= B_) return;
    int lane = threadIdx.x & 31;
    int e = lane & 7, s = lane >> 3;

    const float* gr = g_g + (size_t)b * GH_;
    float acc = 0.f;
    int k0 = s * (GH_ / 4);
    #pragma unroll 4
    for (int k = k0; k < k0 + GH_ / 4; k++)
        acc = fmaf(gr[k], gw2[k * E_ + e], acc);
    acc += __shfl_xor_sync(0xffffffffu, acc, 8);
    acc += __shfl_xor_sync(0xffffffffu, acc, 16);
    float logit = acc + gb2[e];

    float m = logit;
    for (int o = 4; o; o >>= 1) m = fmaxf(m, __shfl_xor_sync(0xffffffffu, m, o));
    float p = (lane < E_) ? expf(logit - m) : 0.f;
    float ssum = p;
    for (int o = 16; o; o >>= 1) ssum += __shfl_xor_sync(0xffffffffu, ssum, o);
    float prob = p / ssum;
    if (lane < E_) dout[OFF_GATE + (size_t)b * E_ + lane] = prob;

    float v1 = (lane < E_) ? prob : -1.f; int i1 = lane;
    for (int o = 16; o; o >>= 1) {
        float ov = __shfl_xor_sync(0xffffffffu, v1, o);
        int   oi = __shfl_xor_sync(0xffffffffu, i1, o);
        if (ov > v1 || (ov == v1 && oi < i1)) { v1 = ov; i1 = oi; }
    }
    float v2 = (lane < E_ && lane != i1) ? prob : -1.f; int i2 = lane;
    for (int o = 16; o; o >>= 1) {
        float ov = __shfl_xor_sync(0xffffffffu, v2, o);
        int   oi = __shfl_xor_sync(0xffffffffu, i2, o);
        if (ov > v2 || (ov == v2 && oi < i2)) { v2 = ov; i2 = oi; }
    }
    if (lane == 0) {
        float sw = v1 + v2;
        g_tw[b * 2 + 0] = v1 / sw;
        g_tw[b * 2 + 1] = v2 / sw;
        g_ti[b * 2 + 0] = i1;
        g_ti[b * 2 + 1] = i2;
    }
}

// ---------------------------------------------------------------------------
extern "C" void kernel_launch(void* const* d_in, const int* in_sizes, int n_in,
                              void* d_out, int out_size) {
    const float* x     = (const float*)d_in[0];
    const float* gamma = (const float*)d_in[1];
    const float* beta  = (const float*)d_in[2];
    const float* gw1   = (const float*)d_in[3];
    const float* gb1   = (const float*)d_in[4];
    const float* gw2   = (const float*)d_in[5];
    const float* gb2   = (const float*)d_in[6];
    const float* ew1   = (const float*)d_in[7];
    const float* eb1   = (const float*)d_in[8];
    const float* ew2   = (const float*)d_in[9];
    const float* eb2   = (const float*)d_in[10];
    float* out = (float*)d_out;

    float *pg;
    __nv_bfloat16 *phhi, *phlo, *pgw1hi, *pgw1lo;
    __half *phf, *pw1f, *pw2f, *phidf;
    cudaGetSymbolAddress((void**)&pg,     g_g);
    cudaGetSymbolAddress((void**)&phhi,   g_hhi);
    cudaGetSymbolAddress((void**)&phlo,   g_hlo);
    cudaGetSymbolAddress((void**)&pgw1hi, g_gw1hi);
    cudaGetSymbolAddress((void**)&pgw1lo, g_gw1lo);
    cudaGetSymbolAddress((void**)&phf,    g_hf);
    cudaGetSymbolAddress((void**)&pw1f,   g_w1f);
    cudaGetSymbolAddress((void**)&pw2f,   g_w2f);
    cudaGetSymbolAddress((void**)&phidf,  g_hidf);

    cudaFuncSetAttribute(gemm_f16<2>, cudaFuncAttributeMaxDynamicSharedMemorySize, SMEM_F);
    cudaFuncSetAttribute(gemm_f16<3>, cudaFuncAttributeMaxDynamicSharedMemorySize, SMEM_F);
    cudaFuncSetAttribute(gemm_gate,   cudaFuncAttributeMaxDynamicSharedMemorySize, SMEM_TC);

    // 1. LayerNorm: bf16 split (gating) + fp16 (experts)
    ln_kernel<<<B_, 256>>>(x, gamma, beta);

    // 2. ew1 transpose (fp16)
    transpose_f16_kernel<<<dim3(H_ / 32, D_ / 32, E_), dim3(32, 8)>>>(ew1, pw1f, D_, H_);

    // 3. Expert GEMM1 (fp16, 128x128): hid[e] = gelu(h @ ew1[e] + eb1[e])
    gemm_f16<2><<<dim3(H_ / 128, B_ / 128, E_), 256, SMEM_F>>>(
        phf, pw1f, eb1,
        phidf, nullptr, nullptr,
        D_, 0, (size_t)H_ * D_, H_,
        (size_t)B_ * H_, H_, 0);

    // 4. Gating path (exact bf16x3): transpose, GEMM, softmax/top-2
    transpose_split_kernel<<<dim3(GH_ / 32, D_ / 32, 1), dim3(32, 8)>>>(gw1, pgw1hi, pgw1lo, D_, GH_);
    gemm_gate<<<dim3(GH_ / 128, B_ / 128, 1), 256, SMEM_TC>>>(
        phhi, phlo, pgw1hi, pgw1lo, gb1, pg, D_, GH_);
    gate_kernel<<<(B_ + 7) / 8, 256>>>(gw2, gb2, out);

    // 5. ew2 transpose (fp16) + zero result region (async memset, capturable)
    transpose_f16_kernel<<<dim3(D_ / 32, H_ / 32, E_), dim3(32, 8)>>>(ew2, pw2f, H_, D_);
    cudaMemsetAsync(out, 0, (size_t)B_ * D_ * sizeof(float));

    // 6. Expert GEMM2 (fp16, 128x128) + fused top-k combine
    gemm_f16<3><<<dim3(D_ / 128, B_ / 128, E_), 256, SMEM_F>>>(
        phidf, pw2f, eb2,
        nullptr, out + OFF_EO, out,
        H_, (size_t)B_ * H_, (size_t)D_ * H_, D_,
        0, E_ * D_, D_);
}

// round 17
// speedup vs baseline: 1.0805x; 1.0805x over previous
#include <cuda_runtime.h>
#include <cuda_bf16.h>
#include <cuda_fp16.h>
#include <math.h>
#include <stdint.h>

#define B_  8192
#define D_  768
#define GH_ 384
#define E_  8
#define H_  3072

#define OFF_GATE ((size_t)B_ * D_)
#define OFF_EO   (OFF_GATE + (size_t)B_ * E_)

// Scratch
__device__ float g_g[(size_t)B_ * GH_];
__device__ __align__(16) __nv_bfloat16 g_hhi[(size_t)B_ * D_];   // gating path (exact)
__device__ __align__(16) __nv_bfloat16 g_hlo[(size_t)B_ * D_];
__device__ __align__(16) __nv_bfloat16 g_gw1hi[(size_t)GH_ * D_];
__device__ __align__(16) __nv_bfloat16 g_gw1lo[(size_t)GH_ * D_];
__device__ __align__(16) __half g_hf[(size_t)B_ * D_];           // fp16 expert path
__device__ __align__(16) __half g_w1f[(size_t)E_ * H_ * D_];
__device__ __align__(16) __half g_w2f[(size_t)E_ * D_ * H_];
__device__ __align__(16) __half g_hidf[(size_t)E_ * B_ * H_];
__device__ float g_tw[B_ * 2];
__device__ int   g_ti[B_ * 2];

__device__ __forceinline__ uint32_t smem_to_u32(const void* p) {
    uint32_t a;
    asm("{ .reg .u64 t; cvta.to.shared.u64 t, %1; cvt.u32.u64 %0, t; }" : "=r"(a) : "l"(p));
    return a;
}
// Fast exact-form gelu (A&S 7.1.26 erf, abs err 1.5e-7)
__device__ __forceinline__ float gelu_fast(float x) {
    float xs = x * 0.7071067811865476f;
    float ax = fabsf(xs);
    float t  = __fdividef(1.0f, fmaf(0.3275911f, ax, 1.0f));
    float y  = t * fmaf(t, fmaf(t, fmaf(t, fmaf(t, 1.061405429f, -1.453152027f),
                                        1.421413741f), -0.284496736f), 0.254829592f);
    float ev = 1.0f - y * __expf(-ax * ax);
    ev = copysignf(ev, xs);
    return 0.5f * x * (1.0f + ev);
}
__device__ __forceinline__ void splitbf(float v, __nv_bfloat16& h, __nv_bfloat16& l) {
    h = __float2bfloat16(v);
    l = __float2bfloat16(v - __bfloat162float(h));
}
__device__ __forceinline__ uint32_t packh2(float v0, float v1) {
    uint32_t p;
    asm("cvt.rn.f16x2.f32 %0, %1, %2;" : "=r"(p) : "f"(v1), "f"(v0));
    return p;  // lo half = v0
}
__device__ __forceinline__ void cpa16(uint32_t dst, const void* src) {
    asm volatile("cp.async.cg.shared.global [%0], [%1], 16;" :: "r"(dst), "l"(src));
}
#define CP_COMMIT() asm volatile("cp.async.commit_group;" ::: "memory")
#define CP_WAIT1()  asm volatile("cp.async.wait_group 1;" ::: "memory")
#define CP_WAIT0()  asm volatile("cp.async.wait_group 0;" ::: "memory")

#define LDSM4(r, addr)                                                          \
    asm volatile("ldmatrix.sync.aligned.m8n8.x4.shared.b16 {%0,%1,%2,%3}, [%4];"\
                 : "=r"((r)[0]), "=r"((r)[1]), "=r"((r)[2]), "=r"((r)[3])       \
                 : "r"(addr))

#define MMA_BF16(d, a, b0, b1)                                                  \
    asm volatile("mma.sync.aligned.m16n8k16.row.col.f32.bf16.bf16.f32 "         \
                 "{%0,%1,%2,%3}, {%4,%5,%6,%7}, {%8,%9}, {%0,%1,%2,%3};"        \
                 : "+f"((d)[0]), "+f"((d)[1]), "+f"((d)[2]), "+f"((d)[3])       \
                 : "r"((a)[0]), "r"((a)[1]), "r"((a)[2]), "r"((a)[3]),          \
                   "r"(b0), "r"(b1))

#define MMA_F16(d, a, b0, b1)                                                   \
    asm volatile("mma.sync.aligned.m16n8k16.row.col.f32.f16.f16.f32 "           \
                 "{%0,%1,%2,%3}, {%4,%5,%6,%7}, {%8,%9}, {%0,%1,%2,%3};"        \
                 : "+f"((d)[0]), "+f"((d)[1]), "+f"((d)[2]), "+f"((d)[3])       \
                 : "r"((a)[0]), "r"((a)[1]), "r"((a)[2]), "r"((a)[3]),          \
                   "r"(b0), "r"(b1))

// ---------------------------------------------------------------------------
// LayerNorm: bf16 hi/lo (gating) + fp16 single plane (experts)
// ---------------------------------------------------------------------------
__global__ void ln_kernel(const float* __restrict__ x,
                          const float* __restrict__ gamma,
                          const float* __restrict__ beta) {
    int b = blockIdx.x;
    const float* row = x + (size_t)b * D_;
    float s = 0.f, s2 = 0.f;
    for (int i = threadIdx.x; i < D_; i += blockDim.x) {
        float v = row[i];
        s += v; s2 += v * v;
    }
    __shared__ float red[64];
    for (int o = 16; o; o >>= 1) {
        s  += __shfl_down_sync(0xffffffffu, s,  o);
        s2 += __shfl_down_sync(0xffffffffu, s2, o);
    }
    int wid = threadIdx.x >> 5, lid = threadIdx.x & 31;
    if (lid == 0) { red[wid] = s; red[wid + 32] = s2; }
    __syncthreads();
    int nw = blockDim.x >> 5;
    if (wid == 0) {
        s  = (lid < nw) ? red[lid]      : 0.f;
        s2 = (lid < nw) ? red[lid + 32] : 0.f;
        for (int o = 16; o; o >>= 1) {
            s  += __shfl_down_sync(0xffffffffu, s,  o);
            s2 += __shfl_down_sync(0xffffffffu, s2, o);
        }
        if (lid == 0) { red[0] = s; red[1] = s2; }
    }
    __syncthreads();
    float mu   = red[0] / D_;
    float var  = red[1] / D_ - mu * mu;
    float rstd = rsqrtf(var + 1e-5f);
    for (int i = threadIdx.x; i < D_; i += blockDim.x) {
        float v = (row[i] - mu) * rstd * gamma[i] + beta[i];
        size_t idx = (size_t)b * D_ + i;
        __nv_bfloat16 hi, lo;
        splitbf(v, hi, lo);
        g_hhi[idx] = hi;
        g_hlo[idx] = lo;
        g_hf[idx]  = __float2half_rn(v);
    }
}

// ---------------------------------------------------------------------------
// Transposes: fp16 single-plane (expert weights) and bf16 split (gating)
// ---------------------------------------------------------------------------
__global__ void transpose_f16_kernel(const float* __restrict__ src,
                                     __half* __restrict__ dst, int R, int C) {
    __shared__ float t[32][33];
    int e = blockIdx.z;
    int c0 = blockIdx.x * 32, r0 = blockIdx.y * 32;
    const float* s = src + (size_t)e * R * C;
    #pragma unroll
    for (int i = 0; i < 32; i += 8)
        t[threadIdx.y + i][threadIdx.x] =
            s[(size_t)(r0 + threadIdx.y + i) * C + c0 + threadIdx.x];
    __syncthreads();
    size_t ob = (size_t)e * C * R;
    #pragma unroll
    for (int i = 0; i < 32; i += 8)
        dst[ob + (size_t)(c0 + threadIdx.y + i) * R + r0 + threadIdx.x] =
            __float2half_rn(t[threadIdx.x][threadIdx.y + i]);
}

__global__ void transpose_split_kernel(const float* __restrict__ src,
                                       __nv_bfloat16* __restrict__ dhi,
                                       __nv_bfloat16* __restrict__ dlo,
                                       int R, int C) {
    __shared__ float t[32][33];
    int c0 = blockIdx.x * 32, r0 = blockIdx.y * 32;
    #pragma unroll
    for (int i = 0; i < 32; i += 8)
        t[threadIdx.y + i][threadIdx.x] =
            src[(size_t)(r0 + threadIdx.y + i) * C + c0 + threadIdx.x];
    __syncthreads();
    #pragma unroll
    for (int i = 0; i < 32; i += 8) {
        float v = t[threadIdx.x][threadIdx.y + i];
        __nv_bfloat16 hi, lo;
        splitbf(v, hi, lo);
        size_t o = (size_t)(c0 + threadIdx.y + i) * R + r0 + threadIdx.x;
        dhi[o] = hi;
        dlo[o] = lo;
    }
}

// ---------------------------------------------------------------------------
// fp16 single-plane GEMM: 128x128x64 CTA chunks, 8 warps 64x32, 256 thr,
// 128B-pitch SW128-swizzled smem (seg ^= row&7), 3-stage pipeline, 2 CTAs/SM.
// OUT_MODE: 2 = gelu + fp16 out (GEMM1), 3 = fp32 +bias + fused combine (GEMM2)
// ---------------------------------------------------------------------------
#define FPLANE 16384                     // 128 rows * 128B
#define FSTAGE (2 * FPLANE)              // A|B = 32768
#define FNSTG 3
#define SMEM_F (FNSTG * FSTAGE)          // 98304

template <int OUT_MODE>
__global__ void __launch_bounds__(256, 2) gemm_f16(
    const __half* __restrict__ Ah, const __half* __restrict__ Bh,
    const float* __restrict__ bias,
    __half* __restrict__ OutH, float* __restrict__ OutF, float* __restrict__ Res,
    int Ktot, size_t aStrideE, size_t bStrideE, size_t biasStrideE,
    size_t cStrideE, int ldc, int cColStride)
{
    extern __shared__ char smem[];
    uint32_t sbase = smem_to_u32(smem);
    int tid  = threadIdx.x;
    int warp = tid >> 5, lane = tid & 31;
    int e  = blockIdx.z;
    int bm = blockIdx.y * 128;
    int bn = blockIdx.x * 128;
    int wm = (warp >> 2) * 64;
    int wn = (warp & 3)  * 32;
    int g  = lane >> 2, tg = lane & 3;
    int mi = lane >> 3, rr = lane & 7;

    const __half* pA = Ah + (size_t)e * aStrideE + (size_t)bm * Ktot;
    const __half* pB = Bh + (size_t)e * bStrideE + (size_t)bn * Ktot;

    // ldmatrix lane addressing (128B pitch, seg ^= row&7 on 16B segments)
    int arow = wm + (mi & 1) * 8 + rr;
    uint32_t aoff = (uint32_t)arow * 128;
    int aswz = arow & 7;
    int akseg = mi >> 1;                 // 16B half within each k16 step
    int brow = wn + (mi >> 1) * 8 + rr;
    uint32_t boff = (uint32_t)brow * 128;
    int bswz = brow & 7;
    int bkseg = mi & 1;

    float acc[4][4][4];
    #pragma unroll
    for (int i = 0; i < 4; i++)
        #pragma unroll
        for (int j = 0; j < 4; j++)
            #pragma unroll
            for (int r = 0; r < 4; r++) acc[i][j][r] = 0.f;

    const int NC = Ktot / 64;

    auto load_chunk = [&](int c, int st) {
        int k0 = c * 64;
        uint32_t sb = sbase + (uint32_t)st * FSTAGE;
        #pragma unroll
        for (int i = 0; i < 4; i++) {            // 1024 16B units per plane
            int p = tid + i * 256;
            int row = p >> 3, seg = p & 7;
            uint32_t d = sb + (uint32_t)row * 128
                       + (uint32_t)((seg ^ (row & 7)) << 4);
            size_t go = (size_t)row * Ktot + k0 + seg * 8;
            cpa16(d,          pA + go);
            cpa16(d + FPLANE, pB + go);
        }
        CP_COMMIT();
    };

    load_chunk(0, 0);
    if (NC > 1) load_chunk(1, 1);

    for (int c = 0; c < NC; c++) {
        if (c + 1 < NC) { CP_WAIT1(); } else { CP_WAIT0(); }
        __syncthreads();
        // Stage (c+2)%3 consumed in iter c-1 (ordered by sync above): refill now.
        if (c + 2 < NC) load_chunk(c + 2, (c + 2) % FNSTG);

        uint32_t sb = sbase + (uint32_t)((c % FNSTG) * FSTAGE);
        #pragma unroll
        for (int ks = 0; ks < 4; ks++) {         // 4 k16 steps per chunk
            uint32_t af[4][4], bf[2][4];
            #pragma unroll
            for (int i = 0; i < 4; i++) {
                uint32_t ad = sb + aoff + (uint32_t)i * 2048
                            + (uint32_t)(((ks * 2 + akseg) ^ aswz) << 4);
                LDSM4(af[i], ad);
            }
            #pragma unroll
            for (int jp = 0; jp < 2; jp++) {
                uint32_t bd = sb + FPLANE + boff + (uint32_t)jp * 2048
                            + (uint32_t)(((ks * 2 + bkseg) ^ bswz) << 4);
                LDSM4(bf[jp], bd);
            }
            #pragma unroll
            for (int i = 0; i < 4; i++)
                #pragma unroll
                for (int j = 0; j < 4; j++) {
                    int jp = j >> 1, hf = (j & 1) * 2;
                    MMA_F16(acc[i][j], af[i], bf[jp][hf], bf[jp][hf + 1]);
                }
        }
    }

    const float* bp = bias + (size_t)e * biasStrideE;
    #pragma unroll
    for (int i = 0; i < 4; i++) {
        int r0 = bm + wm + i * 16 + g;
        float cw0 = 0.f, cw1 = 0.f;
        if (OUT_MODE == 3) {
            int i00 = g_ti[r0 * 2], i01 = g_ti[r0 * 2 + 1];
            cw0 = (i00 == e) ? g_tw[r0 * 2] : ((i01 == e) ? g_tw[r0 * 2 + 1] : 0.f);
            int r1 = r0 + 8;
            int i10 = g_ti[r1 * 2], i11 = g_ti[r1 * 2 + 1];
            cw1 = (i10 == e) ? g_tw[r1 * 2] : ((i11 == e) ? g_tw[r1 * 2 + 1] : 0.f);
        }
        #pragma unroll
        for (int j = 0; j < 4; j++) {
            int c0 = bn + wn + j * 8 + tg * 2;
            float bi0 = bp[c0], bi1 = bp[c0 + 1];
            float v0 = acc[i][j][0] + bi0, v1 = acc[i][j][1] + bi1;
            float v2 = acc[i][j][2] + bi0, v3 = acc[i][j][3] + bi1;
            size_t rbA = (size_t)e * cStrideE + (size_t)r0 * ldc
                       + (size_t)e * cColStride + c0;
            size_t rbB = rbA + (size_t)8 * ldc;
            if (OUT_MODE == 3) {
                *(float2*)(OutF + rbA) = make_float2(v0, v1);
                *(float2*)(OutF + rbB) = make_float2(v2, v3);
                if (cw0 != 0.f) {
                    atomicAdd(&Res[(size_t)r0 * D_ + c0],     cw0 * v0);
                    atomicAdd(&Res[(size_t)r0 * D_ + c0 + 1], cw0 * v1);
                }
                if (cw1 != 0.f) {
                    atomicAdd(&Res[(size_t)(r0 + 8) * D_ + c0],     cw1 * v2);
                    atomicAdd(&Res[(size_t)(r0 + 8) * D_ + c0 + 1], cw1 * v3);
                }
            } else {  // OUT_MODE 2: gelu + fp16
                v0 = gelu_fast(v0); v1 = gelu_fast(v1);
                v2 = gelu_fast(v2); v3 = gelu_fast(v3);
                *(uint32_t*)(OutH + rbA) = packh2(v0, v1);
                *(uint32_t*)(OutH + rbB) = packh2(v2, v3);
            }
        }
    }
}

// ---------------------------------------------------------------------------
// Exact bf16x3 gating GEMM (unchanged, gelu fp32 out)
// ---------------------------------------------------------------------------
#define PLANE_B 8192
#define STAGE_B (4 * PLANE_B)
#define NSTG 3
#define SMEM_TC (NSTG * STAGE_B)

__global__ void __launch_bounds__(256, 2) gemm_gate(
    const __nv_bfloat16* __restrict__ Ahi, const __nv_bfloat16* __restrict__ Alo,
    const __nv_bfloat16* __restrict__ Bhi, const __nv_bfloat16* __restrict__ Blo,
    const float* __restrict__ bias, float* __restrict__ OutF,
    int Ktot, int ldc)
{
    extern __shared__ char smem[];
    uint32_t sbase = smem_to_u32(smem);
    int tid  = threadIdx.x;
    int warp = tid >> 5, lane = tid & 31;
    int bm = blockIdx.y * 128;
    int bn = blockIdx.x * 128;
    int wm = (warp >> 2) * 64;
    int wn = (warp & 3)  * 32;
    int g  = lane >> 2, tg = lane & 3;
    int mi = lane >> 3, rr = lane & 7;

    const __nv_bfloat16* pAhi = Ahi + (size_t)bm * Ktot;
    const __nv_bfloat16* pAlo = Alo + (size_t)bm * Ktot;
    const __nv_bfloat16* pBhi = Bhi + (size_t)bn * Ktot;
    const __nv_bfloat16* pBlo = Blo + (size_t)bn * Ktot;

    int arow = wm + (mi & 1) * 8 + rr;
    uint32_t aoff = (uint32_t)arow * 64;
    uint32_t aswz = (uint32_t)(((arow >> 1) & 3) << 4);
    int akseg = mi >> 1;
    int brow = wn + (mi >> 1) * 8 + rr;
    uint32_t boff = (uint32_t)brow * 64;
    uint32_t bswz = (uint32_t)(((brow >> 1) & 3) << 4);
    int bkseg = mi & 1;

    float acc[4][4][4];
    #pragma unroll
    for (int i = 0; i < 4; i++)
        #pragma unroll
        for (int j = 0; j < 4; j++)
            #pragma unroll
            for (int r = 0; r < 4; r++) acc[i][j][r] = 0.f;

    const int NC = Ktot / 32;

    auto load_chunk = [&](int c, int st) {
        int k0 = c * 32;
        uint32_t sb = sbase + (uint32_t)st * STAGE_B;
        #pragma unroll
        for (int i = 0; i < 2; i++) {
            int p = tid + i * 256;
            int row = p >> 2, col = p & 3;
            uint32_t d = sb + (uint32_t)row * 64
                       + (uint32_t)((col ^ ((row >> 1) & 3)) << 4);
            size_t go = (size_t)row * Ktot + k0 + col * 8;
            cpa16(d,                 pAhi + go);
            cpa16(d + PLANE_B,       pAlo + go);
            cpa16(d + 2u * PLANE_B,  pBhi + go);
            cpa16(d + 3u * PLANE_B,  pBlo + go);
        }
        CP_COMMIT();
    };

    load_chunk(0, 0);
    if (NC > 1) load_chunk(1, 1);

    for (int c = 0; c < NC; c++) {
        if (c + 1 < NC) { CP_WAIT1(); } else { CP_WAIT0(); }
        __syncthreads();
        if (c + 2 < NC) load_chunk(c + 2, (c + 2) % NSTG);

        uint32_t sb = sbase + (uint32_t)((c % NSTG) * STAGE_B);
        #pragma unroll
        for (int ks = 0; ks < 2; ks++) {
            uint32_t ah[4][4], al[4][4], bh[2][4], bl[2][4];
            #pragma unroll
            for (int i = 0; i < 4; i++) {
                uint32_t ad = sb + aoff + (uint32_t)i * 1024
                            + (((uint32_t)(ks * 2 + akseg) << 4) ^ aswz);
                LDSM4(ah[i], ad);
                LDSM4(al[i], ad + PLANE_B);
            }
            #pragma unroll
            for (int jp = 0; jp < 2; jp++) {
                uint32_t bd = sb + 2u * PLANE_B + boff + (uint32_t)jp * 1024
                            + (((uint32_t)(ks * 2 + bkseg) << 4) ^ bswz);
                LDSM4(bh[jp], bd);
                LDSM4(bl[jp], bd + PLANE_B);
            }
            #pragma unroll
            for (int i = 0; i < 4; i++)
                #pragma unroll
                for (int j = 0; j < 4; j++) {
                    int jp = j >> 1, hf = (j & 1) * 2;
                    MMA_BF16(acc[i][j], ah[i], bh[jp][hf], bh[jp][hf + 1]);
                }
            #pragma unroll
            for (int i = 0; i < 4; i++)
                #pragma unroll
                for (int j = 0; j < 4; j++) {
                    int jp = j >> 1, hf = (j & 1) * 2;
                    MMA_BF16(acc[i][j], ah[i], bl[jp][hf], bl[jp][hf + 1]);
                }
            #pragma unroll
            for (int i = 0; i < 4; i++)
                #pragma unroll
                for (int j = 0; j < 4; j++) {
                    int jp = j >> 1, hf = (j & 1) * 2;
                    MMA_BF16(acc[i][j], al[i], bh[jp][hf], bh[jp][hf + 1]);
                }
        }
    }

    #pragma unroll
    for (int i = 0; i < 4; i++) {
        int r0 = bm + wm + i * 16 + g;
        #pragma unroll
        for (int j = 0; j < 4; j++) {
            int c0 = bn + wn + j * 8 + tg * 2;
            float bi0 = bias[c0], bi1 = bias[c0 + 1];
            size_t rbA = (size_t)r0 * ldc + c0;
            size_t rbB = rbA + (size_t)8 * ldc;
            OutF[rbA]     = gelu_fast(acc[i][j][0] + bi0);
            OutF[rbA + 1] = gelu_fast(acc[i][j][1] + bi1);
            OutF[rbB]     = gelu_fast(acc[i][j][2] + bi0);
            OutF[rbB + 1] = gelu_fast(acc[i][j][3] + bi1);
        }
    }
}

// ---------------------------------------------------------------------------
__global__ void gate_kernel(const float* __restrict__ gw2,
                            const float* __restrict__ gb2,
                            float* __restrict__ dout) {
    int b = blockIdx.x * (blockDim.x >> 5) + (threadIdx.x >> 5);
    if (b >= B_) return;
    int lane = threadIdx.x & 31;
    int e = lane & 7, s = lane >> 3;

    const float* gr = g_g + (size_t)b * GH_;
    float acc = 0.f;
    int k0 = s * (GH_ / 4);
    #pragma unroll 4
    for (int k = k0; k < k0 + GH_ / 4; k++)
        acc = fmaf(gr[k], gw2[k * E_ + e], acc);
    acc += __shfl_xor_sync(0xffffffffu, acc, 8);
    acc += __shfl_xor_sync(0xffffffffu, acc, 16);
    float logit = acc + gb2[e];

    float m = logit;
    for (int o = 4; o; o >>= 1) m = fmaxf(m, __shfl_xor_sync(0xffffffffu, m, o));
    float p = (lane < E_) ? expf(logit - m) : 0.f;
    float ssum = p;
    for (int o = 16; o; o >>= 1) ssum += __shfl_xor_sync(0xffffffffu, ssum, o);
    float prob = p / ssum;
    if (lane < E_) dout[OFF_GATE + (size_t)b * E_ + lane] = prob;

    float v1 = (lane < E_) ? prob : -1.f; int i1 = lane;
    for (int o = 16; o; o >>= 1) {
        float ov = __shfl_xor_sync(0xffffffffu, v1, o);
        int   oi = __shfl_xor_sync(0xffffffffu, i1, o);
        if (ov > v1 || (ov == v1 && oi < i1)) { v1 = ov; i1 = oi; }
    }
    float v2 = (lane < E_ && lane != i1) ? prob : -1.f; int i2 = lane;
    for (int o = 16; o; o >>= 1) {
        float ov = __shfl_xor_sync(0xffffffffu, v2, o);
        int   oi = __shfl_xor_sync(0xffffffffu, i2, o);
        if (ov > v2 || (ov == v2 && oi < i2)) { v2 = ov; i2 = oi; }
    }
    if (lane == 0) {
        float sw = v1 + v2;
        g_tw[b * 2 + 0] = v1 / sw;
        g_tw[b * 2 + 1] = v2 / sw;
        g_ti[b * 2 + 0] = i1;
        g_ti[b * 2 + 1] = i2;
    }
}

// ---------------------------------------------------------------------------
extern "C" void kernel_launch(void* const* d_in, const int* in_sizes, int n_in,
                              void* d_out, int out_size) {
    const float* x     = (const float*)d_in[0];
    const float* gamma = (const float*)d_in[1];
    const float* beta  = (const float*)d_in[2];
    const float* gw1   = (const float*)d_in[3];
    const float* gb1   = (const float*)d_in[4];
    const float* gw2   = (const float*)d_in[5];
    const float* gb2   = (const float*)d_in[6];
    const float* ew1   = (const float*)d_in[7];
    const float* eb1   = (const float*)d_in[8];
    const float* ew2   = (const float*)d_in[9];
    const float* eb2   = (const float*)d_in[10];
    float* out = (float*)d_out;

    float *pg;
    __nv_bfloat16 *phhi, *phlo, *pgw1hi, *pgw1lo;
    __half *phf, *pw1f, *pw2f, *phidf;
    cudaGetSymbolAddress((void**)&pg,     g_g);
    cudaGetSymbolAddress((void**)&phhi,   g_hhi);
    cudaGetSymbolAddress((void**)&phlo,   g_hlo);
    cudaGetSymbolAddress((void**)&pgw1hi, g_gw1hi);
    cudaGetSymbolAddress((void**)&pgw1lo, g_gw1lo);
    cudaGetSymbolAddress((void**)&phf,    g_hf);
    cudaGetSymbolAddress((void**)&pw1f,   g_w1f);
    cudaGetSymbolAddress((void**)&pw2f,   g_w2f);
    cudaGetSymbolAddress((void**)&phidf,  g_hidf);

    cudaFuncSetAttribute(gemm_f16<2>, cudaFuncAttributeMaxDynamicSharedMemorySize, SMEM_F);
    cudaFuncSetAttribute(gemm_f16<3>, cudaFuncAttributeMaxDynamicSharedMemorySize, SMEM_F);
    cudaFuncSetAttribute(gemm_gate,   cudaFuncAttributeMaxDynamicSharedMemorySize, SMEM_TC);

    // 1. LayerNorm: bf16 split (gating) + fp16 (experts)
    ln_kernel<<<B_, 256>>>(x, gamma, beta);

    // 2. ew1 transpose (fp16)
    transpose_f16_kernel<<<dim3(H_ / 32, D_ / 32, E_), dim3(32, 8)>>>(ew1, pw1f, D_, H_);

    // 3. Expert GEMM1 (fp16, 128x128): hid[e] = gelu(h @ ew1[e] + eb1[e])
    gemm_f16<2><<<dim3(H_ / 128, B_ / 128, E_), 256, SMEM_F>>>(
        phf, pw1f, eb1,
        phidf, nullptr, nullptr,
        D_, 0, (size_t)H_ * D_, H_,
        (size_t)B_ * H_, H_, 0);

    // 4. Gating path (exact bf16x3): transpose, GEMM, softmax/top-2
    transpose_split_kernel<<<dim3(GH_ / 32, D_ / 32, 1), dim3(32, 8)>>>(gw1, pgw1hi, pgw1lo, D_, GH_);
    gemm_gate<<<dim3(GH_ / 128, B_ / 128, 1), 256, SMEM_TC>>>(
        phhi, phlo, pgw1hi, pgw1lo, gb1, pg, D_, GH_);
    gate_kernel<<<(B_ + 7) / 8, 256>>>(gw2, gb2, out);

    // 5. ew2 transpose (fp16) + zero result region (async memset, capturable)
    transpose_f16_kernel<<<dim3(D_ / 32, H_ / 32, E_), dim3(32, 8)>>>(ew2, pw2f, H_, D_);
    cudaMemsetAsync(out, 0, (size_t)B_ * D_ * sizeof(float));

    // 6. Expert GEMM2 (fp16, 128x128) + fused top-k combine
    gemm_f16<3><<<dim3(D_ / 128, B_ / 128, E_), 256, SMEM_F>>>(
        phidf, pw2f, eb2,
        nullptr, out + OFF_EO, out,
        H_, (size_t)B_ * H_, (size_t)D_ * H_, D_,
        0, E_ * D_, D_);
}